// round 3
// baseline (speedup 1.0000x reference)
#include <cuda_runtime.h>
#include <cuda_bf16.h>

// out = mean( (box9(pred) - box9(target))^2 ), zero-padded on H,W.
// box9(pred)-box9(target) = box9(pred-target); separable 9x9 box:
// 9-wide horizontal sum, then 9-tall vertical sliding sum; /81^2 at the end.
//
// 64 images of 512x512. One block = 256 output cols x 64 output rows.
// Grid = 2 x 8 x 64 = 1024 blocks, 256 threads.
// Per batch of 8 input rows: LDG diff -> s_d; hsums (3x LDS.128 -> 4 hsums)
// -> 16-row s_h ring; persistent vertical sliding window (1 add + 1 sub LDS
// per output row per column).

#define Wd    512
#define Hd    512
#define NIMG  64
#define TW    256
#define IWd   264                 // TW + 8 halo
#define TH    64
#define NBLK  (2 * 8 * NIMG)      // 1024
#define RING  16
#define NTOT  16777216.0

__device__ double        g_sum  = 0.0;
__device__ unsigned int  g_done = 0;

__global__ __launch_bounds__(256, 4)
void pooled_mse_kernel(const float* __restrict__ pred,
                       const float* __restrict__ target,
                       float* __restrict__ out) {
    __shared__ float s_d[8 * IWd];       // 8.25 KB: diff rows of current batch
    __shared__ float s_h[RING * TW];     // 16 KB:  hsum ring

    const int tid = threadIdx.x;
    const int X0  = blockIdx.x * TW;     // 0 or 256
    const int y0  = blockIdx.y * TH;
    const int img = blockIdx.z;

    const size_t ibase = (size_t)img * (Hd * Wd);
    const float* pbase = pred + ibase;
    const float* tbase = target + ibase;

    float acc = 0.0f;
    float vs  = 0.0f;                    // persistent vertical 9-window sum

    #pragma unroll 1
    for (int b = 0; b < 9; b++) {
        // ---- load batch b: input rows abs (y0-4+8b)..+7, cols X0-4..X0+259
        // 8 rows x 66 float4 = 528 tasks
        #pragma unroll
        for (int i = tid; i < 528; i += 256) {
            const int row = i / 66;
            const int q   = i - row * 66;
            const int gxb = X0 - 4 + (q << 2);
            const int r   = y0 - 4 + b * 8 + row;
            float4 v = make_float4(0.f, 0.f, 0.f, 0.f);
            if ((unsigned)r < (unsigned)Hd && (unsigned)gxb < (unsigned)Wd) {
                const float4 p4 = *(const float4*)(pbase + (size_t)r * Wd + gxb);
                const float4 t4 = *(const float4*)(tbase + (size_t)r * Wd + gxb);
                v = make_float4(p4.x - t4.x, p4.y - t4.y, p4.z - t4.z, p4.w - t4.w);
            }
            *(float4*)(s_d + row * IWd + (q << 2)) = v;
        }
        __syncthreads();

        // ---- horizontal 9-sums: thread (rr, cg) -> rows rr,rr+4; cols 4cg..+3
        {
            const int cg = tid & 63;
            const int rr = tid >> 6;
            const int i0 = cg << 2;
            #pragma unroll
            for (int k = 0; k < 2; k++) {
                const int row = rr + (k << 2);
                const float* drow = s_d + row * IWd;
                const float4 A = *(const float4*)(drow + i0);
                const float4 Bv = *(const float4*)(drow + i0 + 4);
                const float4 C = *(const float4*)(drow + i0 + 8);
                const float h0 = ((A.x + A.y) + (A.z + A.w))
                               + ((Bv.x + Bv.y) + (Bv.z + Bv.w)) + C.x;
                const float h1 = h0 - A.x + C.y;
                const float h2 = h1 - A.y + C.z;
                const float h3 = h2 - A.z + C.w;
                const int ridx = (b * 8 + row) & (RING - 1);
                *(float4*)(s_h + ridx * TW + i0) = make_float4(h0, h1, h2, h3);
            }
        }
        __syncthreads();

        // ---- vertical sliding 9-sum, one column per thread ----
        if (b == 1) {
            // init: sum of hsum rows rel 0..7 (slots 0..7)
            float s = 0.0f;
            #pragma unroll
            for (int k = 0; k < 8; k++) s += s_h[k * TW + tid];
            vs = s;
        }
        if (b >= 1) {
            // output rows rel 8(b-1)+k: add row rel 8b+k, then sub row rel 8(b-1)+k
            #pragma unroll
            for (int k = 0; k < 8; k++) {
                const int sa = (b * 8 + k) & (RING - 1);
                const int ss = ((b - 1) * 8 + k) & (RING - 1);
                const float ha = s_h[sa * TW + tid];
                const float hs = s_h[ss * TW + tid];
                vs += ha;
                acc += vs * vs;
                vs -= hs;
            }
        }
    }

    // ---- block reduction ----
    __syncthreads();
    #pragma unroll
    for (int off = 16; off > 0; off >>= 1)
        acc += __shfl_xor_sync(0xFFFFFFFFu, acc, off);
    float* s_red = s_d;
    const int warp = tid >> 5;
    const int lane = tid & 31;
    if (lane == 0) s_red[warp] = acc;
    __syncthreads();
    if (warp == 0) {
        float v = (lane < 8) ? s_red[lane] : 0.0f;
        #pragma unroll
        for (int off = 4; off > 0; off >>= 1)
            v += __shfl_xor_sync(0xFFFFFFFFu, v, off);
        if (lane == 0) {
            atomicAdd(&g_sum, (double)v);
            __threadfence();
            const unsigned old = atomicAdd(&g_done, 1u);
            if (old == NBLK - 1) {
                const double s = *((volatile double*)&g_sum);
                out[0] = (float)(s / (81.0 * 81.0) / NTOT);
                g_sum  = 0.0;     // reset for next graph replay
                g_done = 0u;
            }
        }
    }
}

extern "C" void kernel_launch(void* const* d_in, const int* in_sizes, int n_in,
                              void* d_out, int out_size) {
    const float* pred   = (const float*)d_in[0];
    const float* target = (const float*)d_in[1];
    float* out = (float*)d_out;
    dim3 grid(2, 8, NIMG);            // 1024 blocks
    pooled_mse_kernel<<<grid, 256>>>(pred, target, out);
}

// round 4
// speedup vs baseline: 1.1646x; 1.1646x over previous
#include <cuda_runtime.h>
#include <cuda_bf16.h>

// out = mean( (box9(pred) - box9(target))^2 ), zero-padded on H,W.
// box9(pred)-box9(target) = box9(pred-target); separable 9x9 box:
// 9-wide horizontal sum then 9-tall vertical sliding sum; /81^2 at the end.
//
// 64 images of 512x512 f32. One block = full width (512) x 32 output rows.
// Grid = 16 strips x 64 images = 1024 blocks, 256 threads.
// Per 8-row batch, software-pipelined with register prefetch:
//   STS cur diff -> s_d ; LDG next batch -> regs ; sync ;
//   hsum (2 LDS.128 + own reg) -> 16-row ring ; sync ;
//   persistent vertical sliding 9-sum (regs), square+acc.

#define Wd    512
#define Hd    512
#define TH    32
#define NB    5                    // input batches per block (40 rows)
#define RING  16
#define NBLK  (16 * 64)            // 1024
#define NTOT  16777216.0

__device__ double        g_sum  = 0.0;
__device__ unsigned int  g_done = 0;

__global__ __launch_bounds__(256, 4)
void pooled_mse_kernel(const float* __restrict__ pred,
                       const float* __restrict__ target,
                       float* __restrict__ out) {
    __shared__ float s_d[8 * Wd];        // 16 KB: diff rows of current batch
    __shared__ float s_h[RING * Wd];     // 32 KB: hsum ring

    const int tid      = threadIdx.x;
    const int y0       = blockIdx.x * TH;    // strip origin
    const int img      = blockIdx.y;
    const int row_base = tid >> 7;           // 0 or 1
    const int x0       = (tid & 127) << 2;   // 0..508

    const size_t ibase = (size_t)img * (Hd * Wd);
    const float* pbase = pred + ibase;
    const float* tbase = target + ibase;

    float acc = 0.0f;
    float2 vs = make_float2(0.f, 0.f);       // persistent vertical window sum
    const int c0 = tid << 1;                 // 2 columns per thread for vsum

    float4 cur[4], nxt[4];

    // prologue: load batch 0 (input rows rel -4..3)
    #pragma unroll
    for (int k = 0; k < 4; k++) {
        const int r = y0 - 4 + row_base + 2 * k;
        float4 v = make_float4(0.f, 0.f, 0.f, 0.f);
        if ((unsigned)r < (unsigned)Hd) {
            const float4 p4 = *(const float4*)(pbase + (size_t)r * Wd + x0);
            const float4 t4 = *(const float4*)(tbase + (size_t)r * Wd + x0);
            v = make_float4(p4.x - t4.x, p4.y - t4.y, p4.z - t4.z, p4.w - t4.w);
        }
        cur[k] = v;
    }

    #pragma unroll
    for (int b = 0; b < NB; b++) {
        // ---- stage cur batch to smem ----
        #pragma unroll
        for (int k = 0; k < 4; k++)
            *(float4*)(s_d + (row_base + 2 * k) * Wd + x0) = cur[k];

        // ---- prefetch next batch (overlaps both syncs + compute) ----
        if (b < NB - 1) {
            #pragma unroll
            for (int k = 0; k < 4; k++) {
                const int r = y0 - 4 + (b + 1) * 8 + row_base + 2 * k;
                float4 v = make_float4(0.f, 0.f, 0.f, 0.f);
                if ((unsigned)r < (unsigned)Hd) {
                    const float4 p4 = *(const float4*)(pbase + (size_t)r * Wd + x0);
                    const float4 t4 = *(const float4*)(tbase + (size_t)r * Wd + x0);
                    v = make_float4(p4.x - t4.x, p4.y - t4.y, p4.z - t4.z, p4.w - t4.w);
                }
                nxt[k] = v;
            }
        }
        __syncthreads();   // s_d complete; prev vsum done reading ring

        // ---- horizontal 9-sums (neighbors from smem, middle from reg) ----
        #pragma unroll
        for (int k = 0; k < 4; k++) {
            const int row = row_base + 2 * k;
            const float* drow = s_d + row * Wd;
            const float4 A = (x0 == 0)
                ? make_float4(0.f, 0.f, 0.f, 0.f)
                : *(const float4*)(drow + x0 - 4);
            const float4 C = (x0 == 508)
                ? make_float4(0.f, 0.f, 0.f, 0.f)
                : *(const float4*)(drow + x0 + 4);
            const float4 Bv = cur[k];
            const float h0 = ((A.x + A.y) + (A.z + A.w))
                           + ((Bv.x + Bv.y) + (Bv.z + Bv.w)) + C.x;
            const float h1 = h0 - A.x + C.y;
            const float h2 = h1 - A.y + C.z;
            const float h3 = h2 - A.z + C.w;
            const int slot = (b * 8 + row) & (RING - 1);
            *(float4*)(s_h + slot * Wd + x0) = make_float4(h0, h1, h2, h3);
        }
        __syncthreads();   // ring rows of batch b visible

        // ---- vertical sliding 9-sum ----
        if (b == 1) {
            float2 s = make_float2(0.f, 0.f);
            #pragma unroll
            for (int k = 0; k < 8; k++) {
                const float2 h = *(const float2*)(s_h + k * Wd + c0);
                s.x += h.x; s.y += h.y;
            }
            vs = s;
        }
        if (b >= 1) {
            #pragma unroll
            for (int k = 0; k < 8; k++) {
                const int sa = (b * 8 + k) & (RING - 1);
                const int ss = ((b - 1) * 8 + k) & (RING - 1);
                const float2 ha = *(const float2*)(s_h + sa * Wd + c0);
                const float2 hb = *(const float2*)(s_h + ss * Wd + c0);
                vs.x += ha.x; vs.y += ha.y;
                acc += vs.x * vs.x + vs.y * vs.y;
                vs.x -= hb.x; vs.y -= hb.y;
            }
        }

        #pragma unroll
        for (int k = 0; k < 4; k++) cur[k] = nxt[k];
    }

    // ---- block reduction ----
    __syncthreads();
    #pragma unroll
    for (int off = 16; off > 0; off >>= 1)
        acc += __shfl_xor_sync(0xFFFFFFFFu, acc, off);
    float* s_red = s_d;
    const int warp = tid >> 5;
    const int lane = tid & 31;
    if (lane == 0) s_red[warp] = acc;
    __syncthreads();
    if (warp == 0) {
        float v = (lane < 8) ? s_red[lane] : 0.0f;
        #pragma unroll
        for (int off = 4; off > 0; off >>= 1)
            v += __shfl_xor_sync(0xFFFFFFFFu, v, off);
        if (lane == 0) {
            atomicAdd(&g_sum, (double)v);
            __threadfence();
            const unsigned old = atomicAdd(&g_done, 1u);
            if (old == NBLK - 1) {
                const double s = *((volatile double*)&g_sum);
                out[0] = (float)(s / (81.0 * 81.0) / NTOT);
                g_sum  = 0.0;     // reset for next graph replay
                g_done = 0u;
            }
        }
    }
}

extern "C" void kernel_launch(void* const* d_in, const int* in_sizes, int n_in,
                              void* d_out, int out_size) {
    const float* pred   = (const float*)d_in[0];
    const float* target = (const float*)d_in[1];
    float* out = (float*)d_out;
    dim3 grid(16, 64);               // strips x images = 1024 blocks
    pooled_mse_kernel<<<grid, 256>>>(pred, target, out);
}

// round 5
// speedup vs baseline: 1.2634x; 1.0849x over previous
#include <cuda_runtime.h>
#include <cstdint>

// out = mean( (box9(pred) - box9(target))^2 ), zero-padded on H,W.
// box9(pred)-box9(target) = box9(pred-target); separable 9x9 box.
//
// TMA (cp.async.bulk 1D) streams raw pred/target rows into a 3-slot smem
// ring (groups of 4 full-width rows). Consumers: 4 warps x 128 cols; each
// thread owns 4 cols; diff + horizontal 9-sum via shuffles; vertical 9-sum
// as a register ring; square+accumulate. No LDG, no hsum smem ring.

#define Wd      512
#define Hd      512
#define TH      32
#define NSTRIP  16
#define NIMG    64
#define NBLK    (NSTRIP * NIMG)       // 1024
#define NGRP    10                    // groups of 4 input rows (40 rows)
#define SLOTS   3
#define ROWB    2048                  // bytes per row (512 f32)
#define GRPB    (4 * ROWB)            // 8KB per tensor per group
#define NTOT    16777216.0

// dynamic smem: pbuf[SLOTS][4][512] | tbuf[SLOTS][4][512] | 3 mbarriers
#define PT_FLOATS (SLOTS * 4 * Wd)    // 6144
#define BAR_OFF   (2 * PT_FLOATS * 4) // 49152 bytes
#define SMEM_BYTES (BAR_OFF + 64)

__device__ double       g_sum  = 0.0;
__device__ unsigned int g_done = 0;

static __device__ __forceinline__ uint32_t s2u(const void* p) {
    uint32_t a;
    asm("{ .reg .u64 t; cvta.to.shared.u64 t, %1; cvt.u32.u64 %0, t; }"
        : "=r"(a) : "l"(p));
    return a;
}

static __device__ __forceinline__ void mbar_init(uint32_t mb, uint32_t cnt) {
    asm volatile("mbarrier.init.shared.b64 [%0], %1;" :: "r"(mb), "r"(cnt) : "memory");
}
static __device__ __forceinline__ void mbar_expect_tx(uint32_t mb, uint32_t bytes) {
    asm volatile("mbarrier.arrive.expect_tx.shared.b64 _, [%0], %1;"
                 :: "r"(mb), "r"(bytes) : "memory");
}
static __device__ __forceinline__ void bulk_g2s(uint32_t dst, const void* src,
                                                uint32_t bytes, uint32_t mb) {
    asm volatile(
        "cp.async.bulk.shared::cta.global.mbarrier::complete_tx::bytes [%0], [%1], %2, [%3];"
        :: "r"(dst), "l"(src), "r"(bytes), "r"(mb) : "memory");
}
static __device__ __forceinline__ void mbar_wait(uint32_t mb, uint32_t parity) {
    asm volatile(
        "{\n\t"
        ".reg .pred P1;\n\t"
        "WL_%=:\n\t"
        "mbarrier.try_wait.parity.acquire.cta.shared::cta.b64 P1, [%0], %1, 0x989680;\n\t"
        "@P1 bra.uni WD_%=;\n\t"
        "bra.uni WL_%=;\n\t"
        "WD_%=:\n\t"
        "}"
        :: "r"(mb), "r"(parity) : "memory");
}

// issue group G's TMA loads (rows y0-4+4G .. +3, clamped to [0,Hd))
static __device__ __forceinline__ void issue_group(
    int G, int y0, const float* pimg, const float* timg,
    uint32_t pbuf_u32, uint32_t tbuf_u32, uint32_t bar_u32)
{
    const int rbase = y0 - 4 + 4 * G;
    int i0 = rbase < 0 ? -rbase : 0;
    int i1 = (rbase + 4 > Hd) ? (Hd - rbase) : 4;
    if (i1 < i0) i1 = i0;
    const int n = i1 - i0;
    const int slot = G % SLOTS;
    const uint32_t mb = bar_u32 + slot * 8;
    mbar_expect_tx(mb, (uint32_t)(n * ROWB * 2));
    if (n > 0) {
        const uint32_t off = (uint32_t)(slot * 4 + i0) * ROWB;
        const size_t gofs = (size_t)(rbase + i0) * Wd;
        bulk_g2s(pbuf_u32 + off, pimg + gofs, (uint32_t)(n * ROWB), mb);
        bulk_g2s(tbuf_u32 + off, timg + gofs, (uint32_t)(n * ROWB), mb);
    }
}

__global__ __launch_bounds__(128)
void pooled_mse_kernel(const float* __restrict__ pred,
                       const float* __restrict__ target,
                       float* __restrict__ out) {
    extern __shared__ float sm[];
    float* pbuf = sm;                       // [SLOTS][4][512]
    float* tbuf = sm + PT_FLOATS;           // [SLOTS][4][512]
    __shared__ float s_red[4];

    const uint32_t sbase    = s2u(sm);
    const uint32_t pbuf_u32 = sbase;
    const uint32_t tbuf_u32 = sbase + PT_FLOATS * 4;
    const uint32_t bar_u32  = sbase + BAR_OFF;

    const int tid  = threadIdx.x;
    const int lane = tid & 31;
    const int y0   = blockIdx.x * TH;
    const int img  = blockIdx.y;
    const int x0   = tid << 2;              // 4 cols per thread, 0..508

    const float* pimg = pred   + (size_t)img * (Hd * Wd);
    const float* timg = target + (size_t)img * (Hd * Wd);

    if (tid == 0) {
        mbar_init(bar_u32 + 0, 1);
        mbar_init(bar_u32 + 8, 1);
        mbar_init(bar_u32 + 16, 1);
    }
    __syncthreads();
    if (tid == 0) {
        issue_group(0, y0, pimg, timg, pbuf_u32, tbuf_u32, bar_u32);
        issue_group(1, y0, pimg, timg, pbuf_u32, tbuf_u32, bar_u32);
        issue_group(2, y0, pimg, timg, pbuf_u32, tbuf_u32, bar_u32);
    }

    float4 Hring[9];
    float4 vs = make_float4(0.f, 0.f, 0.f, 0.f);
    float  acc = 0.0f;

    #pragma unroll
    for (int g = 0; g < NGRP; g++) {
        const int slot = g % SLOTS;
        mbar_wait(bar_u32 + slot * 8, (uint32_t)((g / SLOTS) & 1));

        #pragma unroll
        for (int i = 0; i < 4; i++) {
            const int r    = g * 4 + i;          // 0..39 (compile-time)
            const int rabs = y0 - 4 + r;
            const bool valid = ((unsigned)rabs < (unsigned)Hd);

            const float* prow = pbuf + (slot * 4 + i) * Wd;
            const float* trow = tbuf + (slot * 4 + i) * Wd;

            float4 d = make_float4(0.f, 0.f, 0.f, 0.f);
            if (valid) {
                const float4 p = *(const float4*)(prow + x0);
                const float4 t = *(const float4*)(trow + x0);
                d = make_float4(p.x - t.x, p.y - t.y, p.z - t.z, p.w - t.w);
            }

            float4 dl, dr;
            dl.x = __shfl_up_sync(0xFFFFFFFFu, d.x, 1);
            dl.y = __shfl_up_sync(0xFFFFFFFFu, d.y, 1);
            dl.z = __shfl_up_sync(0xFFFFFFFFu, d.z, 1);
            dl.w = __shfl_up_sync(0xFFFFFFFFu, d.w, 1);
            dr.x = __shfl_down_sync(0xFFFFFFFFu, d.x, 1);
            dr.y = __shfl_down_sync(0xFFFFFFFFu, d.y, 1);
            dr.z = __shfl_down_sync(0xFFFFFFFFu, d.z, 1);
            dr.w = __shfl_down_sync(0xFFFFFFFFu, d.w, 1);
            if (lane == 0) {                      // cross-warp / image-left halo
                dl = make_float4(0.f, 0.f, 0.f, 0.f);
                if (valid && x0 != 0) {
                    const float4 p = *(const float4*)(prow + x0 - 4);
                    const float4 t = *(const float4*)(trow + x0 - 4);
                    dl = make_float4(p.x - t.x, p.y - t.y, p.z - t.z, p.w - t.w);
                }
            }
            if (lane == 31) {                     // cross-warp / image-right halo
                dr = make_float4(0.f, 0.f, 0.f, 0.f);
                if (valid && x0 != Wd - 4) {
                    const float4 p = *(const float4*)(prow + x0 + 4);
                    const float4 t = *(const float4*)(trow + x0 + 4);
                    dr = make_float4(p.x - t.x, p.y - t.y, p.z - t.z, p.w - t.w);
                }
            }

            const float h0 = ((dl.x + dl.y) + (dl.z + dl.w))
                           + ((d.x + d.y) + (d.z + d.w)) + dr.x;
            const float h1 = h0 - dl.x + dr.y;
            const float h2 = h1 - dl.y + dr.z;
            const float h3 = h2 - dl.z + dr.w;
            const float4 hv = make_float4(h0, h1, h2, h3);
            Hring[r % 9] = hv;

            vs.x += h0; vs.y += h1; vs.z += h2; vs.w += h3;
            if (r >= 8) {
                acc += vs.x * vs.x + vs.y * vs.y + vs.z * vs.z + vs.w * vs.w;
                const float4 ho = Hring[(r - 8) % 9];
                vs.x -= ho.x; vs.y -= ho.y; vs.z -= ho.z; vs.w -= ho.w;
            }
        }
        __syncthreads();                          // slot free
        if (g + SLOTS < NGRP && tid == 0)
            issue_group(g + SLOTS, y0, pimg, timg, pbuf_u32, tbuf_u32, bar_u32);
    }

    // ---- block reduction (128 threads) ----
    #pragma unroll
    for (int off = 16; off > 0; off >>= 1)
        acc += __shfl_xor_sync(0xFFFFFFFFu, acc, off);
    const int warp = tid >> 5;
    if (lane == 0) s_red[warp] = acc;
    __syncthreads();
    if (warp == 0) {
        float v = (lane < 4) ? s_red[lane] : 0.0f;
        v += __shfl_xor_sync(0xFFFFFFFFu, v, 2);
        v += __shfl_xor_sync(0xFFFFFFFFu, v, 1);
        if (lane == 0) {
            atomicAdd(&g_sum, (double)v);
            __threadfence();
            const unsigned old = atomicAdd(&g_done, 1u);
            if (old == NBLK - 1) {
                const double s = *((volatile double*)&g_sum);
                out[0] = (float)(s / (81.0 * 81.0) / NTOT);
                g_sum  = 0.0;                     // reset for next graph replay
                g_done = 0u;
            }
        }
    }
}

extern "C" void kernel_launch(void* const* d_in, const int* in_sizes, int n_in,
                              void* d_out, int out_size) {
    const float* pred   = (const float*)d_in[0];
    const float* target = (const float*)d_in[1];
    float* out = (float*)d_out;
    cudaFuncSetAttribute(pooled_mse_kernel,
                         cudaFuncAttributeMaxDynamicSharedMemorySize, SMEM_BYTES);
    dim3 grid(NSTRIP, NIMG);                      // 1024 blocks
    pooled_mse_kernel<<<grid, 128, SMEM_BYTES>>>(pred, target, out);
}